// round 1
// baseline (speedup 1.0000x reference)
#include <cuda_runtime.h>

// Problem dims (fixed by setup_inputs): B=256, Q=256, S=512, D=1024
#define NB 256
#define NQ 256
#define NS 512
#define ND 1024

#define EPS 1e-8f
#define SLOPE 0.1f
#define SMOOTH 9.0f

// Small scratch (allowed: __device__ globals, no allocation)
__device__ float g_invnorm[NB * NS];  // 1/(||row||+eps) per (b,s)
__device__ float g_invden[NB * NQ];   // 1/softmax_denominator per (b,q)

// ---------------------------------------------------------------------------
// K1: P[b,s,q] = leaky_relu( sum_d ctx[b,s,d] * qry[b,q,d] )
// NT gemm: both operands K(D)-major. 64x64 tile, BK=16, 256 thr, 4x4/thread.
// ---------------------------------------------------------------------------
__global__ __launch_bounds__(256) void k_scores(
    const float* __restrict__ qry, const float* __restrict__ ctx,
    float* __restrict__ P) {
  __shared__ float As[16][68];  // ctx tile, transposed: As[k][s_local]
  __shared__ float Bs[16][68];  // qry tile, transposed: Bs[k][q_local]

  const int b  = blockIdx.z;
  const int s0 = blockIdx.y * 64;
  const int q0 = blockIdx.x * 64;

  const float* Cb = ctx + ((size_t)b * NS + s0) * ND;
  const float* Qb = qry + ((size_t)b * NQ + q0) * ND;

  const int t  = threadIdx.x;
  const int lr = t >> 2;         // 0..63: row within tile
  const int lc = (t & 3) << 2;   // 0,4,8,12: k-offset of float4
  const int ty = t >> 4;         // 0..15
  const int tx = t & 15;         // 0..15
  const int ty4 = ty << 2, tx4 = tx << 2;

  float acc[4][4];
#pragma unroll
  for (int i = 0; i < 4; i++)
#pragma unroll
    for (int j = 0; j < 4; j++) acc[i][j] = 0.0f;

  for (int k0 = 0; k0 < ND; k0 += 16) {
    float4 a = *(const float4*)(Cb + (size_t)lr * ND + k0 + lc);
    float4 q = *(const float4*)(Qb + (size_t)lr * ND + k0 + lc);
    As[lc + 0][lr] = a.x; As[lc + 1][lr] = a.y;
    As[lc + 2][lr] = a.z; As[lc + 3][lr] = a.w;
    Bs[lc + 0][lr] = q.x; Bs[lc + 1][lr] = q.y;
    Bs[lc + 2][lr] = q.z; Bs[lc + 3][lr] = q.w;
    __syncthreads();
#pragma unroll
    for (int k = 0; k < 16; k++) {
      float a0 = As[k][ty4 + 0], a1 = As[k][ty4 + 1];
      float a2 = As[k][ty4 + 2], a3 = As[k][ty4 + 3];
      float b0 = Bs[k][tx4 + 0], b1 = Bs[k][tx4 + 1];
      float b2 = Bs[k][tx4 + 2], b3 = Bs[k][tx4 + 3];
      acc[0][0] += a0 * b0; acc[0][1] += a0 * b1; acc[0][2] += a0 * b2; acc[0][3] += a0 * b3;
      acc[1][0] += a1 * b0; acc[1][1] += a1 * b1; acc[1][2] += a1 * b2; acc[1][3] += a1 * b3;
      acc[2][0] += a2 * b0; acc[2][1] += a2 * b1; acc[2][2] += a2 * b2; acc[2][3] += a2 * b3;
      acc[3][0] += a3 * b0; acc[3][1] += a3 * b1; acc[3][2] += a3 * b2; acc[3][3] += a3 * b3;
    }
    __syncthreads();
  }

  float* Pb = P + (size_t)b * NS * NQ;
#pragma unroll
  for (int i = 0; i < 4; i++) {
    float4 v;
    float x;
    x = acc[i][0]; v.x = x > 0.0f ? x : SLOPE * x;
    x = acc[i][1]; v.y = x > 0.0f ? x : SLOPE * x;
    x = acc[i][2]; v.z = x > 0.0f ? x : SLOPE * x;
    x = acc[i][3]; v.w = x > 0.0f ? x : SLOPE * x;
    *(float4*)(Pb + (size_t)(s0 + ty4 + i) * NQ + q0 + tx4) = v;
  }
}

// ---------------------------------------------------------------------------
// K2: per-(b,s) row l2 norm over Q=256 contiguous floats. One warp per row.
// ---------------------------------------------------------------------------
__global__ __launch_bounds__(256) void k_rownorm(const float* __restrict__ P) {
  const int row  = blockIdx.x * 8 + (threadIdx.x >> 5);
  const int lane = threadIdx.x & 31;
  const float4* p = (const float4*)(P + (size_t)row * NQ);
  float4 a = p[lane];
  float4 b = p[lane + 32];
  float s = a.x * a.x + a.y * a.y + a.z * a.z + a.w * a.w +
            b.x * b.x + b.y * b.y + b.z * b.z + b.w * b.w;
#pragma unroll
  for (int o = 16; o > 0; o >>= 1) s += __shfl_xor_sync(0xffffffffu, s, o);
  if (lane == 0) g_invnorm[row] = 1.0f / (sqrtf(s) + EPS);
}

// ---------------------------------------------------------------------------
// K3a: softmax denominator over S per (b,q). Logits = 9*P*invnorm in [-9,9],
// so exp is safe without max-subtraction. One block per b, thread = q.
// ---------------------------------------------------------------------------
__global__ __launch_bounds__(256) void k_denom(const float* __restrict__ P) {
  const int b = blockIdx.x;
  const int q = threadIdx.x;
  const float* Pb = P + (size_t)b * NS * NQ + q;
  const float* iv = g_invnorm + b * NS;
  float d0 = 0.f, d1 = 0.f, d2 = 0.f, d3 = 0.f;
#pragma unroll 4
  for (int s = 0; s < NS; s += 4) {
    d0 += __expf(SMOOTH * Pb[(size_t)(s + 0) * NQ] * iv[s + 0]);
    d1 += __expf(SMOOTH * Pb[(size_t)(s + 1) * NQ] * iv[s + 1]);
    d2 += __expf(SMOOTH * Pb[(size_t)(s + 2) * NQ] * iv[s + 2]);
    d3 += __expf(SMOOTH * Pb[(size_t)(s + 3) * NQ] * iv[s + 3]);
  }
  g_invden[b * NQ + q] = 1.0f / (d0 + d1 + d2 + d3);
}

// ---------------------------------------------------------------------------
// K3b: finalize attention in place: A[b,s,q] = exp(9*P*invnorm)*invden.
// float4-vectorized over q.
// ---------------------------------------------------------------------------
__global__ __launch_bounds__(256) void k_final(float* __restrict__ P) {
  const size_t idx4 = (size_t)blockIdx.x * blockDim.x + threadIdx.x;
  const int q4  = (int)(idx4 & 63);         // float4 index within row (NQ/4=64)
  const size_t row = idx4 >> 6;             // b*NS + s
  const int b = (int)(row >> 9);            // /NS
  const float inv = g_invnorm[row];
  const float* id = g_invden + b * NQ + q4 * 4;
  float4 v = ((float4*)P)[idx4];
  v.x = __expf(SMOOTH * v.x * inv) * id[0];
  v.y = __expf(SMOOTH * v.y * inv) * id[1];
  v.z = __expf(SMOOTH * v.z * inv) * id[2];
  v.w = __expf(SMOOTH * v.w * inv) * id[3];
  ((float4*)P)[idx4] = v;
}

// ---------------------------------------------------------------------------
// K4: weighted[b,q,d] = sum_s A[b,s,q] * ctx[b,s,d]
// TN gemm: A is (S,Q) q-contiguous, ctx is (S,D) d-contiguous -> direct smem.
// ---------------------------------------------------------------------------
__global__ __launch_bounds__(256) void k_weighted(
    const float* __restrict__ A, const float* __restrict__ ctx,
    float* __restrict__ W) {
  __shared__ float As[16][68];  // As[k][m] m = q_local
  __shared__ float Bs[16][68];  // Bs[k][n] n = d_local

  const int b  = blockIdx.z;
  const int q0 = blockIdx.y * 64;
  const int d0 = blockIdx.x * 64;

  const float* Ab = A   + (size_t)b * NS * NQ;
  const float* Cb = ctx + (size_t)b * NS * ND;

  const int t  = threadIdx.x;
  const int kk = t >> 4;          // 0..15
  const int m4 = (t & 15) << 2;   // 0..60
  const int ty = t >> 4, tx = t & 15;
  const int ty4 = ty << 2, tx4 = tx << 2;

  float acc[4][4];
#pragma unroll
  for (int i = 0; i < 4; i++)
#pragma unroll
    for (int j = 0; j < 4; j++) acc[i][j] = 0.0f;

  for (int k0 = 0; k0 < NS; k0 += 16) {
    float4 a = *(const float4*)(Ab + (size_t)(k0 + kk) * NQ + q0 + m4);
    float4 c = *(const float4*)(Cb + (size_t)(k0 + kk) * ND + d0 + m4);
    *(float4*)&As[kk][m4] = a;   // row stride 68*4=272B, 16B-aligned
    *(float4*)&Bs[kk][m4] = c;
    __syncthreads();
#pragma unroll
    for (int k = 0; k < 16; k++) {
      float a0 = As[k][ty4 + 0], a1 = As[k][ty4 + 1];
      float a2 = As[k][ty4 + 2], a3 = As[k][ty4 + 3];
      float b0 = Bs[k][tx4 + 0], b1 = Bs[k][tx4 + 1];
      float b2 = Bs[k][tx4 + 2], b3 = Bs[k][tx4 + 3];
      acc[0][0] += a0 * b0; acc[0][1] += a0 * b1; acc[0][2] += a0 * b2; acc[0][3] += a0 * b3;
      acc[1][0] += a1 * b0; acc[1][1] += a1 * b1; acc[1][2] += a1 * b2; acc[1][3] += a1 * b3;
      acc[2][0] += a2 * b0; acc[2][1] += a2 * b1; acc[2][2] += a2 * b2; acc[2][3] += a2 * b3;
      acc[3][0] += a3 * b0; acc[3][1] += a3 * b1; acc[3][2] += a3 * b2; acc[3][3] += a3 * b3;
    }
    __syncthreads();
  }

  float* Wb = W + (size_t)b * NQ * ND;
#pragma unroll
  for (int i = 0; i < 4; i++) {
    float4 v = make_float4(acc[i][0], acc[i][1], acc[i][2], acc[i][3]);
    *(float4*)(Wb + (size_t)(q0 + ty4 + i) * ND + d0 + tx4) = v;
  }
}

// ---------------------------------------------------------------------------
// Launch: d_out = [ weighted (B,Q,D) | attnT (B,S,Q) ]. The attnT region is
// used in place as scratch for the score matrix through K1..K3b.
// ---------------------------------------------------------------------------
extern "C" void kernel_launch(void* const* d_in, const int* in_sizes, int n_in,
                              void* d_out, int out_size) {
  const float* qry = (const float*)d_in[0];  // (B,Q,D)
  const float* ctx = (const float*)d_in[1];  // (B,S,D)
  float* W = (float*)d_out;                            // (B,Q,D)
  float* P = (float*)d_out + (size_t)NB * NQ * ND;     // (B,S,Q)

  {
    dim3 g(NQ / 64, NS / 64, NB);
    k_scores<<<g, 256>>>(qry, ctx, P);
  }
  k_rownorm<<<(NB * NS) / 8, 256>>>(P);
  k_denom<<<NB, 256>>>(P);
  k_final<<<(size_t)NB * NS * NQ / 4 / 256, 256>>>(P);
  {
    dim3 g(ND / 64, NQ / 64, NB);
    k_weighted<<<g, 256>>>(P, ctx, W);
  }
}

// round 6
// speedup vs baseline: 2.3721x; 2.3721x over previous
#include <cuda_runtime.h>
#include <cuda_bf16.h>
#include <cstdint>

// Dims fixed by setup_inputs: B=256, Q=256, S=512, D=1024
#define NB 256
#define NQ 256
#define NS 512
#define ND 1024
#define EPS 1e-8f
#define SLOPE 0.1f
#define SMOOTH 9.0f

__device__ float g_invnorm[NB * NS];
__device__ float g_invden[NB * NQ];

// ---------------------------------------------------------------------------
// helpers
// ---------------------------------------------------------------------------
__device__ __forceinline__ uint32_t smem_u32(const void* p) {
  uint32_t a;
  asm("{ .reg .u64 t; cvta.to.shared.u64 t, %1; cvt.u32.u64 %0, t; }" : "=r"(a) : "l"(p));
  return a;
}

__device__ __forceinline__ void ldsm4(uint32_t* r, uint32_t addr) {
  asm volatile("ldmatrix.sync.aligned.m8n8.x4.shared.b16 {%0,%1,%2,%3}, [%4];"
               : "=r"(r[0]), "=r"(r[1]), "=r"(r[2]), "=r"(r[3]) : "r"(addr));
}
__device__ __forceinline__ void ldsm4t(uint32_t* r, uint32_t addr) {
  asm volatile("ldmatrix.sync.aligned.m8n8.x4.trans.shared.b16 {%0,%1,%2,%3}, [%4];"
               : "=r"(r[0]), "=r"(r[1]), "=r"(r[2]), "=r"(r[3]) : "r"(addr));
}
__device__ __forceinline__ void mma16816(float* c, const uint32_t* a, const uint32_t* b) {
  asm volatile(
      "mma.sync.aligned.m16n8k16.row.col.f32.bf16.bf16.f32 "
      "{%0,%1,%2,%3}, {%4,%5,%6,%7}, {%8,%9}, {%0,%1,%2,%3};"
      : "+f"(c[0]), "+f"(c[1]), "+f"(c[2]), "+f"(c[3])
      : "r"(a[0]), "r"(a[1]), "r"(a[2]), "r"(a[3]), "r"(b[0]), "r"(b[1]));
}

// fp32x4 -> bf16 hi (uint2 = 4 bf16) + bf16 lo residual (uint2)
__device__ __forceinline__ void cvt4(float4 v, uint2& h, uint2& l) {
  float x[4] = {v.x, v.y, v.z, v.w};
  uint16_t hh[4], ll[4];
#pragma unroll
  for (int i = 0; i < 4; i++) {
    __nv_bfloat16 hb = __float2bfloat16_rn(x[i]);
    float r = x[i] - __bfloat162float(hb);
    __nv_bfloat16 lb = __float2bfloat16_rn(r);
    hh[i] = *(uint16_t*)&hb;
    ll[i] = *(uint16_t*)&lb;
  }
  h.x = (uint32_t)hh[0] | ((uint32_t)hh[1] << 16);
  h.y = (uint32_t)hh[2] | ((uint32_t)hh[3] << 16);
  l.x = (uint32_t)ll[0] | ((uint32_t)ll[1] << 16);
  l.y = (uint32_t)ll[2] | ((uint32_t)ll[3] << 16);
}

// ---------------------------------------------------------------------------
// GEMM1: P[s][q] = leakyrelu( sum_d ctx[s][d]*qry[q][d] )
// m = s (A = ctx, K-major), n = q (B = qry, K-major), k = d. Non-trans ldmatrix.
// CTA 128x128, K-chunk 32, 8 warps (2m x 4n), warp tile 64x32.
// ---------------------------------------------------------------------------
#define P1 40  // smem row stride (bf16) for 32-wide K tiles

__global__ __launch_bounds__(256) void k_scores_mma(
    const float* __restrict__ qry, const float* __restrict__ ctx,
    float* __restrict__ P) {
  __shared__ __align__(16) __nv_bfloat16 sAhi[128 * P1], sAlo[128 * P1];
  __shared__ __align__(16) __nv_bfloat16 sBhi[128 * P1], sBlo[128 * P1];

  const int t = threadIdx.x, w = t >> 5, lane = t & 31;
  const int b = blockIdx.z, q0 = blockIdx.x * 128, s0 = blockIdx.y * 128;
  const int warp_m = w >> 2, warp_n = w & 3;

  const int lr = lane >> 3, lc8 = lane & 7;  // gmem load: 4 rows x 32 cols per warp-instr
  const float* Abase = ctx + ((size_t)(b * NS + s0)) * ND;  // rows = s
  const float* Bbase = qry + ((size_t)(b * NQ + q0)) * ND;  // rows = q

  const uint32_t aHi = smem_u32(sAhi), aLo = smem_u32(sAlo);
  const uint32_t bHi = smem_u32(sBhi), bLo = smem_u32(sBlo);

  // ldmatrix lane addressing (non-trans)
  const int g = lane >> 3, r8 = lane & 7;
  const int a_row = (g & 1) * 8 + r8, a_col = (g >> 1) * 8;   // A: {m0k0,m8k0,m0k8,m8k8}
  const int b_row = (g >> 1) * 8 + r8, b_col = (g & 1) * 8;   // B: {n0k0,n0k8,n8k0,n8k8}

  float acc[4][4][4];
#pragma unroll
  for (int i = 0; i < 4; i++)
#pragma unroll
    for (int j = 0; j < 4; j++)
#pragma unroll
      for (int k = 0; k < 4; k++) acc[i][j][k] = 0.0f;

  for (int kc = 0; kc < ND; kc += 32) {
    // load + convert 128x32 fp32 of A and B into hi/lo bf16 smem
#pragma unroll
    for (int r4 = 0; r4 < 4; r4++) {
      const int row = r4 * 32 + w * 4 + lr;
      const int col = lc8 * 4;
      uint2 h, l;
      float4 va = *(const float4*)(Abase + (size_t)row * ND + kc + col);
      cvt4(va, h, l);
      *(uint2*)&sAhi[row * P1 + col] = h;
      *(uint2*)&sAlo[row * P1 + col] = l;
      float4 vb = *(const float4*)(Bbase + (size_t)row * ND + kc + col);
      cvt4(vb, h, l);
      *(uint2*)&sBhi[row * P1 + col] = h;
      *(uint2*)&sBlo[row * P1 + col] = l;
    }
    __syncthreads();

#pragma unroll
    for (int kk = 0; kk < 32; kk += 16) {
      uint32_t bh[2][4], bl[2][4];
#pragma unroll
      for (int np = 0; np < 2; np++) {
        const uint32_t off =
            ((warp_n * 32 + np * 16 + b_row) * P1 + kk + b_col) * 2;
        ldsm4(bh[np], bHi + off);
        ldsm4(bl[np], bLo + off);
      }
#pragma unroll
      for (int mi = 0; mi < 4; mi++) {
        uint32_t ah[4], al[4];
        const uint32_t off =
            ((warp_m * 64 + mi * 16 + a_row) * P1 + kk + a_col) * 2;
        ldsm4(ah, aHi + off);
        ldsm4(al, aLo + off);
#pragma unroll
        for (int nt = 0; nt < 4; nt++) {
          const uint32_t* ph = &bh[nt >> 1][(nt & 1) * 2];
          const uint32_t* pl = &bl[nt >> 1][(nt & 1) * 2];
          mma16816(acc[mi][nt], ah, ph);
          mma16816(acc[mi][nt], ah, pl);
          mma16816(acc[mi][nt], al, ph);
        }
      }
    }
    __syncthreads();
  }

  // epilogue: leaky relu, write P[s][q] (float2 stores)
  const int gm = lane >> 2, tg = lane & 3;
  float* Pb = P + (size_t)b * NS * NQ;
#pragma unroll
  for (int mi = 0; mi < 4; mi++) {
    const int sg = s0 + warp_m * 64 + mi * 16 + gm;
#pragma unroll
    for (int nt = 0; nt < 4; nt++) {
      const int qg = q0 + warp_n * 32 + nt * 8 + tg * 2;
      float* c = acc[mi][nt];
      float2 v0 = make_float2(c[0] > 0.f ? c[0] : SLOPE * c[0],
                              c[1] > 0.f ? c[1] : SLOPE * c[1]);
      float2 v1 = make_float2(c[2] > 0.f ? c[2] : SLOPE * c[2],
                              c[3] > 0.f ? c[3] : SLOPE * c[3]);
      *(float2*)(Pb + (size_t)sg * NQ + qg) = v0;
      *(float2*)(Pb + (size_t)(sg + 8) * NQ + qg) = v1;
    }
  }
}

// ---------------------------------------------------------------------------
// GEMM2: W[q][d] = sum_s attn[s][q]*ctx[s][d]
// m = q (A = attn^T via ldmatrix.trans), n = d (B = ctx^T via trans), k = s.
// Operands stay in natural [s][x] layout in smem.
// ---------------------------------------------------------------------------
#define P2 136  // smem row stride (bf16) for 128-wide tiles

__global__ __launch_bounds__(256) void k_weighted_mma(
    const float* __restrict__ attn, const float* __restrict__ ctx,
    float* __restrict__ W) {
  __shared__ __align__(16) __nv_bfloat16 sAhi[32 * P2], sAlo[32 * P2];
  __shared__ __align__(16) __nv_bfloat16 sBhi[32 * P2], sBlo[32 * P2];

  const int t = threadIdx.x, w = t >> 5, lane = t & 31;
  const int b = blockIdx.z, d0 = blockIdx.x * 128, q0 = blockIdx.y * 128;
  const int warp_m = w >> 2, warp_n = w & 3;

  const int lr = lane >> 3, lc8 = lane & 7;
  const float* Ab = attn + (size_t)b * NS * NQ;
  const float* Bb = ctx + (size_t)b * NS * ND;

  const uint32_t aHi = smem_u32(sAhi), aLo = smem_u32(sAlo);
  const uint32_t bHi = smem_u32(sBhi), bLo = smem_u32(sBlo);

  // ldmatrix.trans lane addressing: rows are k-rows
  const int g = lane >> 3, r8 = lane & 7;
  const int a_k = (g >> 1) * 8 + r8, a_m = (g & 1) * 8;   // {m0k0,m8k0,m0k8,m8k8}
  const int b_k = (g & 1) * 8 + r8, b_n = (g >> 1) * 8;   // {n0k0,n0k8,n8k0,n8k8}

  float acc[4][4][4];
#pragma unroll
  for (int i = 0; i < 4; i++)
#pragma unroll
    for (int j = 0; j < 4; j++)
#pragma unroll
      for (int k = 0; k < 4; k++) acc[i][j][k] = 0.0f;

  for (int sc = 0; sc < NS; sc += 32) {
    // stage 32 s-rows x 128 cols of attn (q-cols) and ctx (d-cols)
    const int row = w * 4 + lr;  // 0..31
#pragma unroll
    for (int cr = 0; cr < 4; cr++) {
      const int col = cr * 32 + lc8 * 4;
      uint2 h, l;
      float4 va = *(const float4*)(Ab + (size_t)(sc + row) * NQ + q0 + col);
      cvt4(va, h, l);
      *(uint2*)&sAhi[row * P2 + col] = h;
      *(uint2*)&sAlo[row * P2 + col] = l;
      float4 vb = *(const float4*)(Bb + (size_t)(sc + row) * ND + d0 + col);
      cvt4(vb, h, l);
      *(uint2*)&sBhi[row * P2 + col] = h;
      *(uint2*)&sBlo[row * P2 + col] = l;
    }
    __syncthreads();

#pragma unroll
    for (int kk = 0; kk < 32; kk += 16) {
      uint32_t bh[2][4], bl[2][4];
#pragma unroll
      for (int np = 0; np < 2; np++) {
        const uint32_t off =
            ((kk + b_k) * P2 + warp_n * 32 + np * 16 + b_n) * 2;
        ldsm4t(bh[np], bHi + off);
        ldsm4t(bl[np], bLo + off);
      }
#pragma unroll
      for (int mi = 0; mi < 4; mi++) {
        uint32_t ah[4], al[4];
        const uint32_t off =
            ((kk + a_k) * P2 + warp_m * 64 + mi * 16 + a_m) * 2;
        ldsm4t(ah, aHi + off);
        ldsm4t(al, aLo + off);
#pragma unroll
        for (int nt = 0; nt < 4; nt++) {
          const uint32_t* ph = &bh[nt >> 1][(nt & 1) * 2];
          const uint32_t* pl = &bl[nt >> 1][(nt & 1) * 2];
          mma16816(acc[mi][nt], ah, ph);
          mma16816(acc[mi][nt], ah, pl);
          mma16816(acc[mi][nt], al, ph);
        }
      }
    }
    __syncthreads();
  }

  const int gm = lane >> 2, tg = lane & 3;
  float* Wb = W + (size_t)b * NQ * ND;
#pragma unroll
  for (int mi = 0; mi < 4; mi++) {
    const int qg = q0 + warp_m * 64 + mi * 16 + gm;
#pragma unroll
    for (int nt = 0; nt < 4; nt++) {
      const int dg = d0 + warp_n * 32 + nt * 8 + tg * 2;
      float* c = acc[mi][nt];
      *(float2*)(Wb + (size_t)qg * ND + dg) = make_float2(c[0], c[1]);
      *(float2*)(Wb + (size_t)(qg + 8) * ND + dg) = make_float2(c[2], c[3]);
    }
  }
}

// ---------------------------------------------------------------------------
// Elementwise kernels (unchanged)
// ---------------------------------------------------------------------------
__global__ __launch_bounds__(256) void k_rownorm(const float* __restrict__ P) {
  const int row = blockIdx.x * 8 + (threadIdx.x >> 5);
  const int lane = threadIdx.x & 31;
  const float4* p = (const float4*)(P + (size_t)row * NQ);
  float4 a = p[lane];
  float4 b = p[lane + 32];
  float s = a.x * a.x + a.y * a.y + a.z * a.z + a.w * a.w +
            b.x * b.x + b.y * b.y + b.z * b.z + b.w * b.w;
#pragma unroll
  for (int o = 16; o > 0; o >>= 1) s += __shfl_xor_sync(0xffffffffu, s, o);
  if (lane == 0) g_invnorm[row] = 1.0f / (sqrtf(s) + EPS);
}

__global__ __launch_bounds__(256) void k_denom(const float* __restrict__ P) {
  const int b = blockIdx.x;
  const int q = threadIdx.x;
  const float* Pb = P + (size_t)b * NS * NQ + q;
  const float* iv = g_invnorm + b * NS;
  float d0 = 0.f, d1 = 0.f, d2 = 0.f, d3 = 0.f;
#pragma unroll 4
  for (int s = 0; s < NS; s += 4) {
    d0 += __expf(SMOOTH * Pb[(size_t)(s + 0) * NQ] * iv[s + 0]);
    d1 += __expf(SMOOTH * Pb[(size_t)(s + 1) * NQ] * iv[s + 1]);
    d2 += __expf(SMOOTH * Pb[(size_t)(s + 2) * NQ] * iv[s + 2]);
    d3 += __expf(SMOOTH * Pb[(size_t)(s + 3) * NQ] * iv[s + 3]);
  }
  g_invden[b * NQ + q] = 1.0f / (d0 + d1 + d2 + d3);
}

__global__ __launch_bounds__(256) void k_final(float* __restrict__ P) {
  const size_t idx4 = (size_t)blockIdx.x * blockDim.x + threadIdx.x;
  const int q4 = (int)(idx4 & 63);
  const size_t row = idx4 >> 6;
  const int b = (int)(row >> 9);
  const float inv = g_invnorm[row];
  const float* id = g_invden + b * NQ + q4 * 4;
  float4 v = ((float4*)P)[idx4];
  v.x = __expf(SMOOTH * v.x * inv) * id[0];
  v.y = __expf(SMOOTH * v.y * inv) * id[1];
  v.z = __expf(SMOOTH * v.z * inv) * id[2];
  v.w = __expf(SMOOTH * v.w * inv) * id[3];
  ((float4*)P)[idx4] = v;
}

// ---------------------------------------------------------------------------
// d_out = [ weighted (B,Q,D) | attnT (B,S,Q) ]; attnT region doubles as
// scratch for the score matrix through the softmax chain.
// ---------------------------------------------------------------------------
extern "C" void kernel_launch(void* const* d_in, const int* in_sizes, int n_in,
                              void* d_out, int out_size) {
  const float* qry = (const float*)d_in[0];  // (B,Q,D)
  const float* ctx = (const float*)d_in[1];  // (B,S,D)
  float* W = (float*)d_out;                         // (B,Q,D)
  float* P = (float*)d_out + (size_t)NB * NQ * ND;  // (B,S,Q)

  {
    dim3 g(NQ / 128, NS / 128, NB);  // (2, 4, 256)
    k_scores_mma<<<g, 256>>>(qry, ctx, P);
  }
  k_rownorm<<<(NB * NS) / 8, 256>>>(P);
  k_denom<<<NB, 256>>>(P);
  k_final<<<(size_t)NB * NS * NQ / 4 / 256, 256>>>(P);
  {
    dim3 g(ND / 128, NQ / 128, NB);  // (8, 2, 256)
    k_weighted_mma<<<g, 256>>>(P, ctx, W);
  }
}